// round 1
// baseline (speedup 1.0000x reference)
#include <cuda_runtime.h>
#include <math.h>

#define B_   4
#define H_   16
#define S_   4096
#define D_   64
#define BH_  64
#define SC_  8           // S-chunks for pass1 split-K
#define RPC_ 512         // rows per chunk (S_/SC_)
#define TS_  64          // smem tile rows

// ---- device scratch (no allocations allowed) ----
__device__ float4 g_tab4[S_ * 8];                 // (cos0,sin0,cos1,sin1) per (s, pair-group)
__device__ float  g_partA[BH_ * SC_ * D_ * D_];   // 8.4 MB split-K partials
__device__ float  g_partK[BH_ * SC_ * D_];
__device__ float  g_A[BH_ * D_ * D_];             // reduced A[d][e]
__device__ float  g_ksum[BH_ * D_];

// Packed fp32x2 FMA — the only route to full fp32 rate on sm_103a (FFMA2).
__device__ __forceinline__ float2 ffma2(float2 a, float2 b, float2 c) {
    float2 d;
    asm("fma.rn.f32x2 %0, %1, %2, %3;"
        : "=l"(*reinterpret_cast<unsigned long long*>(&d))
        : "l"(*reinterpret_cast<unsigned long long*>(&a)),
          "l"(*reinterpret_cast<unsigned long long*>(&b)),
          "l"(*reinterpret_cast<unsigned long long*>(&c)));
    return d;
}

// elu(x)+1, matching jax.nn.elu (expm1 path) exactly in fp32.
__device__ __forceinline__ float elu1(float x) {
    return x > 0.0f ? x + 1.0f : expm1f(x) + 1.0f;
}

// ---- RoPE table: theta computed in f64 like the reference, cos/sin precise f32 ----
__global__ void k_tab() {
    int idx = blockIdx.x * blockDim.x + threadIdx.x;
    if (idx >= S_ * 8) return;
    int t = idx >> 3, j = idx & 7;               // j indexes pair-groups (2 pairs per float4)
    double td = (double)t;
    // pair index i has inv = 10000^(-i/16); here i0 = 2j, i1 = 2j+1
    double inv0 = pow(10000.0, -(double)(2 * j) / 16.0);
    double inv1 = pow(10000.0, -(double)(2 * j + 1) / 16.0);
    float th0 = (float)(td * inv0);
    float th1 = (float)(td * inv1);
    g_tab4[idx] = make_float4(cosf(th0), sinf(th0), cosf(th1), sinf(th1));
}

// ---- Pass 1: A_partial = Kr^T V over a 512-row S-chunk; ksum partials ----
// 64 threads, 8x8 register tile per thread (1 B smem / MAC), FFMA2 inner loop.
__global__ void __launch_bounds__(64) k_pass1(const float* __restrict__ K,
                                              const float* __restrict__ V,
                                              const int*   __restrict__ mask) {
    __shared__ __align__(16) float Ks[TS_ * 64];
    __shared__ __align__(16) float Vs[TS_ * 64];
    __shared__ __align__(16) float red[256];

    int tid = threadIdx.x;
    int sc = blockIdx.x, bh = blockIdx.y;
    int b = bh >> 4;
    int ti = tid >> 3, tj = tid & 7;     // compute-phase tile coords
    int c4 = tid & 15, rr = tid >> 4;    // load-phase coords (fixed col-group per thread)

    const float4* K4 = reinterpret_cast<const float4*>(K) + (size_t)bh * (S_ * 16);
    const float4* V4 = reinterpret_cast<const float4*>(V) + (size_t)bh * (S_ * 16);
    const int* mrow = mask + b * S_;

    float2 acc[4][8];
    #pragma unroll
    for (int p = 0; p < 4; p++)
        #pragma unroll
        for (int c = 0; c < 8; c++) acc[p][c] = make_float2(0.f, 0.f);
    float4 ksacc = make_float4(0.f, 0.f, 0.f, 0.f);

    for (int tt = 0; tt < RPC_ / TS_; tt++) {
        int sbase = sc * RPC_ + tt * TS_;
        // load + transform K (elu+1, mask, RoPE) and V into smem
        #pragma unroll
        for (int kk = 0; kk < 16; kk++) {
            int rl = rr + 4 * kk;
            int s = sbase + rl;
            float m = (float)mrow[s];
            float4 kv = K4[s * 16 + c4];
            float f0 = elu1(kv.x) * m;
            float f1 = elu1(kv.y) * m;
            float f2 = elu1(kv.z) * m;
            float f3 = elu1(kv.w) * m;
            ksacc.x += fabsf(f0); ksacc.y += fabsf(f1);
            ksacc.z += fabsf(f2); ksacc.w += fabsf(f3);
            if (c4 < 8) {  // rotary half: cols 4*c4..4*c4+3 < 32
                float4 t4 = g_tab4[s * 8 + c4];
                float r0 = f0 * t4.x - f1 * t4.y;
                float r1 = f1 * t4.x + f0 * t4.y;
                float r2 = f2 * t4.z - f3 * t4.w;
                float r3 = f3 * t4.z + f2 * t4.w;
                f0 = r0; f1 = r1; f2 = r2; f3 = r3;
            }
            reinterpret_cast<float4*>(Ks)[rl * 16 + c4] = make_float4(f0, f1, f2, f3);
            reinterpret_cast<float4*>(Vs)[rl * 16 + c4] = V4[s * 16 + c4];
        }
        __syncthreads();
        // outer-product accumulate: rows paired for FFMA2
        #pragma unroll 8
        for (int s = 0; s < TS_; s++) {
            float4 ka = reinterpret_cast<const float4*>(Ks)[s * 16 + ti * 2];
            float4 kb = reinterpret_cast<const float4*>(Ks)[s * 16 + ti * 2 + 1];
            float2 k01 = make_float2(ka.x, ka.y);
            float2 k23 = make_float2(ka.z, ka.w);
            float2 k45 = make_float2(kb.x, kb.y);
            float2 k67 = make_float2(kb.z, kb.w);
            #pragma unroll
            for (int c = 0; c < 8; c++) {
                float v = Vs[s * 64 + tj + 8 * c];   // strided cols -> conflict-free
                float2 v2 = make_float2(v, v);
                acc[0][c] = ffma2(k01, v2, acc[0][c]);
                acc[1][c] = ffma2(k23, v2, acc[1][c]);
                acc[2][c] = ffma2(k45, v2, acc[2][c]);
                acc[3][c] = ffma2(k67, v2, acc[3][c]);
            }
        }
        __syncthreads();
    }

    // ksum partials: deterministic fixed-order reduction via smem
    reinterpret_cast<float4*>(red)[tid] = ksacc;   // red[rr][4*c4..+3]
    // stage A tile into Ks for a coalesced global store
    #pragma unroll
    for (int p = 0; p < 4; p++)
        #pragma unroll
        for (int c = 0; c < 8; c++) {
            int d = ti * 8 + 2 * p;
            int e = tj + 8 * c;
            Ks[d * 64 + e]       = acc[p][c].x;
            Ks[(d + 1) * 64 + e] = acc[p][c].y;
        }
    __syncthreads();

    float4* outA4 = reinterpret_cast<float4*>(g_partA + (size_t)(bh * SC_ + sc) * 4096);
    for (int i = tid; i < 1024; i += 64)
        outA4[i] = reinterpret_cast<const float4*>(Ks)[i];
    float kvv = red[tid] + red[64 + tid] + red[128 + tid] + red[192 + tid];
    g_partK[(bh * SC_ + sc) * 64 + tid] = kvv;
}

// ---- fixed-order split-K reduction ----
__global__ void __launch_bounds__(256) k_reduce() {
    int bh = blockIdx.x, tid = threadIdx.x;
    for (int idx = tid; idx < 4096; idx += 256) {
        float s = 0.f;
        #pragma unroll
        for (int p = 0; p < SC_; p++)
            s += g_partA[(size_t)(bh * SC_ + p) * 4096 + idx];
        g_A[bh * 4096 + idx] = s;
    }
    if (tid < 64) {
        float s = 0.f;
        #pragma unroll
        for (int p = 0; p < SC_; p++)
            s += g_partK[(bh * SC_ + p) * 64 + tid];
        g_ksum[bh * 64 + tid] = s;
    }
}

// ---- Pass 2: out[s,:] = (RoPE(elu(Q*c)+1) @ A) / (Qf . ksum) ----
// One lane owns one full row: zero cross-lane traffic; A read as warp-uniform
// broadcast LDS (conflict degree 1); FFMA2 inner product.
__global__ void __launch_bounds__(256, 2) k_pass2(const float* __restrict__ Q,
                                                  float* __restrict__ out) {
    __shared__ __align__(16) float As[4096];
    __shared__ __align__(16) float ksm[64];
    int tid = threadIdx.x;
    int st = blockIdx.x, bh = blockIdx.y;
    for (int i = tid; i < 4096; i += 256)
        As[i] = g_A[bh * 4096 + i];
    if (tid < 64) ksm[tid] = g_ksum[bh * 64 + tid];
    __syncthreads();

    int s = st * 256 + tid;
    const float4* Q4 = reinterpret_cast<const float4*>(Q) + ((size_t)bh * S_ + s) * 16;

    float qf[64];
    float nrm = 0.f;
    #pragma unroll
    for (int j = 0; j < 16; j++) {
        float4 v = Q4[j];
        float f0 = elu1(v.x * 0.125f);
        float f1 = elu1(v.y * 0.125f);
        float f2 = elu1(v.z * 0.125f);
        float f3 = elu1(v.w * 0.125f);
        float4 kv = reinterpret_cast<const float4*>(ksm)[j];  // uniform -> broadcast
        nrm += f0 * kv.x + f1 * kv.y + f2 * kv.z + f3 * kv.w; // norm uses PRE-RoPE Qf
        qf[4 * j] = f0; qf[4 * j + 1] = f1; qf[4 * j + 2] = f2; qf[4 * j + 3] = f3;
    }
    #pragma unroll
    for (int j = 0; j < 8; j++) {
        float4 t4 = g_tab4[s * 8 + j];
        float a = qf[4 * j], b2 = qf[4 * j + 1];
        qf[4 * j]     = a * t4.x - b2 * t4.y;
        qf[4 * j + 1] = b2 * t4.x + a * t4.y;
        a = qf[4 * j + 2]; b2 = qf[4 * j + 3];
        qf[4 * j + 2] = a * t4.z - b2 * t4.w;
        qf[4 * j + 3] = b2 * t4.z + a * t4.w;
    }
    float rinv = 1.0f / nrm;
    float4* outp = reinterpret_cast<float4*>(out) + ((size_t)bh * S_ + s) * 16;

    #pragma unroll 1
    for (int h = 0; h < 2; h++) {     // column halves to bound registers/I$
        float2 acc[16];
        #pragma unroll
        for (int c = 0; c < 16; c++) acc[c] = make_float2(0.f, 0.f);
        #pragma unroll
        for (int k = 0; k < 64; k++) {
            float2 qk = make_float2(qf[k], qf[k]);
            #pragma unroll
            for (int c = 0; c < 8; c++) {
                float4 a4 = reinterpret_cast<const float4*>(As)[k * 16 + h * 8 + c];
                acc[2 * c]     = ffma2(qk, make_float2(a4.x, a4.y), acc[2 * c]);
                acc[2 * c + 1] = ffma2(qk, make_float2(a4.z, a4.w), acc[2 * c + 1]);
            }
        }
        #pragma unroll
        for (int c = 0; c < 8; c++) {
            outp[h * 8 + c] = make_float4(acc[2 * c].x * rinv, acc[2 * c].y * rinv,
                                          acc[2 * c + 1].x * rinv, acc[2 * c + 1].y * rinv);
        }
    }
}

extern "C" void kernel_launch(void* const* d_in, const int* in_sizes, int n_in,
                              void* d_out, int out_size) {
    const float* Q   = (const float*)d_in[0];
    const float* K   = (const float*)d_in[1];
    const float* V   = (const float*)d_in[2];
    const int* mask  = (const int*)d_in[3];
    float* out = (float*)d_out;

    k_tab<<<(S_ * 8 + 255) / 256, 256>>>();
    k_pass1<<<dim3(SC_, BH_), 64>>>(K, V, mask);
    k_reduce<<<BH_, 256>>>();
    k_pass2<<<dim3(S_ / 256, BH_), 256>>>(Q, out);
}

// round 2
// speedup vs baseline: 1.0429x; 1.0429x over previous
#include <cuda_runtime.h>
#include <math.h>

#define B_   4
#define H_   16
#define S_   4096
#define D_   64
#define BH_  64
#define SC_  8           // S-chunks for pass1 split-K
#define RPC_ 512         // rows per chunk (S_/SC_)
#define TS_  64          // smem tile rows

// ---- device scratch (no allocations allowed) ----
__device__ float4 g_tab4[S_ * 8];                 // (cos0,sin0,cos1,sin1) per (s, pair-group)
__device__ float  g_partA[BH_ * SC_ * D_ * D_];   // 8.4 MB split-K partials
__device__ float  g_partK[BH_ * SC_ * D_];
__device__ float  g_A[BH_ * D_ * D_];             // reduced A[d][e]
__device__ float  g_ksum[BH_ * D_];

// Packed fp32x2 FMA — the only route to full fp32 rate on sm_103a (FFMA2).
__device__ __forceinline__ float2 ffma2(float2 a, float2 b, float2 c) {
    float2 d;
    asm("fma.rn.f32x2 %0, %1, %2, %3;"
        : "=l"(*reinterpret_cast<unsigned long long*>(&d))
        : "l"(*reinterpret_cast<unsigned long long*>(&a)),
          "l"(*reinterpret_cast<unsigned long long*>(&b)),
          "l"(*reinterpret_cast<unsigned long long*>(&c)));
    return d;
}

// elu(x)+1, matching jax.nn.elu (expm1 path) exactly in fp32.
__device__ __forceinline__ float elu1(float x) {
    return x > 0.0f ? x + 1.0f : expm1f(x) + 1.0f;
}

// ---- RoPE table: theta computed in f64 like the reference, cos/sin precise f32 ----
__global__ void k_tab() {
    int idx = blockIdx.x * blockDim.x + threadIdx.x;
    if (idx >= S_ * 8) return;
    int t = idx >> 3, j = idx & 7;               // j indexes pair-groups (2 pairs per float4)
    double td = (double)t;
    // pair index i has inv = 10000^(-i/16); here i0 = 2j, i1 = 2j+1
    double inv0 = pow(10000.0, -(double)(2 * j) / 16.0);
    double inv1 = pow(10000.0, -(double)(2 * j + 1) / 16.0);
    float th0 = (float)(td * inv0);
    float th1 = (float)(td * inv1);
    g_tab4[idx] = make_float4(cosf(th0), sinf(th0), cosf(th1), sinf(th1));
}

// ---- Pass 1: A_partial = Kr^T V over a 512-row S-chunk; ksum partials ----
// 64 threads, 8x8 register tile per thread (1 B smem / MAC), FFMA2 inner loop.
__global__ void __launch_bounds__(64) k_pass1(const float* __restrict__ K,
                                              const float* __restrict__ V,
                                              const int*   __restrict__ mask) {
    __shared__ __align__(16) float Ks[TS_ * 64];
    __shared__ __align__(16) float Vs[TS_ * 64];
    __shared__ __align__(16) float red[256];

    int tid = threadIdx.x;
    int sc = blockIdx.x, bh = blockIdx.y;
    int b = bh >> 4;
    int ti = tid >> 3, tj = tid & 7;     // compute-phase tile coords
    int c4 = tid & 15, rr = tid >> 4;    // load-phase coords (fixed col-group per thread)

    const float4* K4 = reinterpret_cast<const float4*>(K) + (size_t)bh * (S_ * 16);
    const float4* V4 = reinterpret_cast<const float4*>(V) + (size_t)bh * (S_ * 16);
    const int* mrow = mask + b * S_;

    float2 acc[4][8];
    #pragma unroll
    for (int p = 0; p < 4; p++)
        #pragma unroll
        for (int c = 0; c < 8; c++) acc[p][c] = make_float2(0.f, 0.f);
    float4 ksacc = make_float4(0.f, 0.f, 0.f, 0.f);

    for (int tt = 0; tt < RPC_ / TS_; tt++) {
        int sbase = sc * RPC_ + tt * TS_;
        // load + transform K (elu+1, mask, RoPE) and V into smem
        #pragma unroll
        for (int kk = 0; kk < 16; kk++) {
            int rl = rr + 4 * kk;
            int s = sbase + rl;
            float m = (float)mrow[s];
            float4 kv = K4[s * 16 + c4];
            float f0 = elu1(kv.x) * m;
            float f1 = elu1(kv.y) * m;
            float f2 = elu1(kv.z) * m;
            float f3 = elu1(kv.w) * m;
            ksacc.x += fabsf(f0); ksacc.y += fabsf(f1);
            ksacc.z += fabsf(f2); ksacc.w += fabsf(f3);
            if (c4 < 8) {  // rotary half: cols 4*c4..4*c4+3 < 32
                float4 t4 = g_tab4[s * 8 + c4];
                float r0 = f0 * t4.x - f1 * t4.y;
                float r1 = f1 * t4.x + f0 * t4.y;
                float r2 = f2 * t4.z - f3 * t4.w;
                float r3 = f3 * t4.z + f2 * t4.w;
                f0 = r0; f1 = r1; f2 = r2; f3 = r3;
            }
            reinterpret_cast<float4*>(Ks)[rl * 16 + c4] = make_float4(f0, f1, f2, f3);
            reinterpret_cast<float4*>(Vs)[rl * 16 + c4] = V4[s * 16 + c4];
        }
        __syncthreads();
        // outer-product accumulate: rows paired for FFMA2
        #pragma unroll 8
        for (int s = 0; s < TS_; s++) {
            float4 ka = reinterpret_cast<const float4*>(Ks)[s * 16 + ti * 2];
            float4 kb = reinterpret_cast<const float4*>(Ks)[s * 16 + ti * 2 + 1];
            float2 k01 = make_float2(ka.x, ka.y);
            float2 k23 = make_float2(ka.z, ka.w);
            float2 k45 = make_float2(kb.x, kb.y);
            float2 k67 = make_float2(kb.z, kb.w);
            #pragma unroll
            for (int c = 0; c < 8; c++) {
                float v = Vs[s * 64 + tj + 8 * c];   // strided cols -> conflict-free
                float2 v2 = make_float2(v, v);
                acc[0][c] = ffma2(k01, v2, acc[0][c]);
                acc[1][c] = ffma2(k23, v2, acc[1][c]);
                acc[2][c] = ffma2(k45, v2, acc[2][c]);
                acc[3][c] = ffma2(k67, v2, acc[3][c]);
            }
        }
        __syncthreads();
    }

    // ksum partials: deterministic fixed-order reduction via smem
    reinterpret_cast<float4*>(red)[tid] = ksacc;   // red[rr][4*c4..+3]
    // stage A tile into Ks for a coalesced global store
    #pragma unroll
    for (int p = 0; p < 4; p++)
        #pragma unroll
        for (int c = 0; c < 8; c++) {
            int d = ti * 8 + 2 * p;
            int e = tj + 8 * c;
            Ks[d * 64 + e]       = acc[p][c].x;
            Ks[(d + 1) * 64 + e] = acc[p][c].y;
        }
    __syncthreads();

    float4* outA4 = reinterpret_cast<float4*>(g_partA + (size_t)(bh * SC_ + sc) * 4096);
    for (int i = tid; i < 1024; i += 64)
        outA4[i] = reinterpret_cast<const float4*>(Ks)[i];
    float kvv = red[tid] + red[64 + tid] + red[128 + tid] + red[192 + tid];
    g_partK[(bh * SC_ + sc) * 64 + tid] = kvv;
}

// ---- fixed-order split-K reduction ----
__global__ void __launch_bounds__(256) k_reduce() {
    int bh = blockIdx.x, tid = threadIdx.x;
    for (int idx = tid; idx < 4096; idx += 256) {
        float s = 0.f;
        #pragma unroll
        for (int p = 0; p < SC_; p++)
            s += g_partA[(size_t)(bh * SC_ + p) * 4096 + idx];
        g_A[bh * 4096 + idx] = s;
    }
    if (tid < 64) {
        float s = 0.f;
        #pragma unroll
        for (int p = 0; p < SC_; p++)
            s += g_partK[(bh * SC_ + p) * 64 + tid];
        g_ksum[bh * 64 + tid] = s;
    }
}

// ---- Pass 2: out[s,:] = (RoPE(elu(Q*c)+1) @ A) / (Qf . ksum) ----
// One lane owns one full row: zero cross-lane traffic; A read as warp-uniform
// broadcast LDS (conflict degree 1); FFMA2 inner product.
__global__ void __launch_bounds__(256, 2) k_pass2(const float* __restrict__ Q,
                                                  float* __restrict__ out) {
    __shared__ __align__(16) float As[4096];
    __shared__ __align__(16) float ksm[64];
    int tid = threadIdx.x;
    int st = blockIdx.x, bh = blockIdx.y;
    for (int i = tid; i < 4096; i += 256)
        As[i] = g_A[bh * 4096 + i];
    if (tid < 64) ksm[tid] = g_ksum[bh * 64 + tid];
    __syncthreads();

    int s = st * 256 + tid;
    const float4* Q4 = reinterpret_cast<const float4*>(Q) + ((size_t)bh * S_ + s) * 16;

    float qf[64];
    float nrm = 0.f;
    #pragma unroll
    for (int j = 0; j < 16; j++) {
        float4 v = Q4[j];
        float f0 = elu1(v.x * 0.125f);
        float f1 = elu1(v.y * 0.125f);
        float f2 = elu1(v.z * 0.125f);
        float f3 = elu1(v.w * 0.125f);
        float4 kv = reinterpret_cast<const float4*>(ksm)[j];  // uniform -> broadcast
        nrm += f0 * kv.x + f1 * kv.y + f2 * kv.z + f3 * kv.w; // norm uses PRE-RoPE Qf
        qf[4 * j] = f0; qf[4 * j + 1] = f1; qf[4 * j + 2] = f2; qf[4 * j + 3] = f3;
    }
    #pragma unroll
    for (int j = 0; j < 8; j++) {
        float4 t4 = g_tab4[s * 8 + j];
        float a = qf[4 * j], b2 = qf[4 * j + 1];
        qf[4 * j]     = a * t4.x - b2 * t4.y;
        qf[4 * j + 1] = b2 * t4.x + a * t4.y;
        a = qf[4 * j + 2]; b2 = qf[4 * j + 3];
        qf[4 * j + 2] = a * t4.z - b2 * t4.w;
        qf[4 * j + 3] = b2 * t4.z + a * t4.w;
    }
    float rinv = 1.0f / nrm;
    float4* outp = reinterpret_cast<float4*>(out) + ((size_t)bh * S_ + s) * 16;

    #pragma unroll 1
    for (int h = 0; h < 2; h++) {     // column halves to bound registers/I$
        float2 acc[16];
        #pragma unroll
        for (int c = 0; c < 16; c++) acc[c] = make_float2(0.f, 0.f);
        #pragma unroll
        for (int k = 0; k < 64; k++) {
            float2 qk = make_float2(qf[k], qf[k]);
            #pragma unroll
            for (int c = 0; c < 8; c++) {
                float4 a4 = reinterpret_cast<const float4*>(As)[k * 16 + h * 8 + c];
                acc[2 * c]     = ffma2(qk, make_float2(a4.x, a4.y), acc[2 * c]);
                acc[2 * c + 1] = ffma2(qk, make_float2(a4.z, a4.w), acc[2 * c + 1]);
            }
        }
        #pragma unroll
        for (int c = 0; c < 8; c++) {
            outp[h * 8 + c] = make_float4(acc[2 * c].x * rinv, acc[2 * c].y * rinv,
                                          acc[2 * c + 1].x * rinv, acc[2 * c + 1].y * rinv);
        }
    }
}

extern "C" void kernel_launch(void* const* d_in, const int* in_sizes, int n_in,
                              void* d_out, int out_size) {
    const float* Q   = (const float*)d_in[0];
    const float* K   = (const float*)d_in[1];
    const float* V   = (const float*)d_in[2];
    const int* mask  = (const int*)d_in[3];
    float* out = (float*)d_out;

    k_tab<<<(S_ * 8 + 255) / 256, 256>>>();
    k_pass1<<<dim3(SC_, BH_), 64>>>(K, V, mask);
    k_reduce<<<BH_, 256>>>();
    k_pass2<<<dim3(S_ / 256, BH_), 256>>>(Q, out);
}

// round 3
// speedup vs baseline: 1.4134x; 1.3553x over previous
#include <cuda_runtime.h>
#include <math.h>

#define B_   4
#define H_   16
#define S_   4096
#define D_   64
#define BH_  64
#define SC1  16          // pass1 split-K chunks
#define CH1  256         // rows per pass1 chunk

// ---- device scratch (no allocations allowed) ----
__device__ float4 g_tab4[S_ * 8];                  // (cos0,sin0,cos1,sin1) per (s, pair-group)
__device__ float  g_partA[BH_ * SC1 * D_ * D_];    // 16.8 MB split-K partials
__device__ float  g_partK[BH_ * SC1 * D_];
__device__ float  g_A[BH_ * D_ * D_];              // reduced A[d][e]
__device__ float  g_ksum[BH_ * D_];

// Packed fp32x2 FMA — the only route to full fp32 rate on sm_103a (FFMA2).
__device__ __forceinline__ float2 ffma2(float2 a, float2 b, float2 c) {
    float2 d;
    asm("fma.rn.f32x2 %0, %1, %2, %3;"
        : "=l"(*reinterpret_cast<unsigned long long*>(&d))
        : "l"(*reinterpret_cast<unsigned long long*>(&a)),
          "l"(*reinterpret_cast<unsigned long long*>(&b)),
          "l"(*reinterpret_cast<unsigned long long*>(&c)));
    return d;
}

__device__ __forceinline__ float elu1(float x) {
    return x > 0.0f ? x + 1.0f : expm1f(x) + 1.0f;
}

// ---- RoPE table: theta in f64 like the reference, precise f32 cos/sin ----
__global__ void k_tab() {
    int idx = blockIdx.x * blockDim.x + threadIdx.x;
    if (idx >= S_ * 8) return;
    int t = idx >> 3, j = idx & 7;
    double td = (double)t;
    double inv0 = pow(10000.0, -(double)(2 * j) / 16.0);
    double inv1 = pow(10000.0, -(double)(2 * j + 1) / 16.0);
    float th0 = (float)(td * inv0);
    float th1 = (float)(td * inv1);
    g_tab4[idx] = make_float4(cosf(th0), sinf(th0), cosf(th1), sinf(th1));
}

// ---- Pass 1: A_partial = Kr^T V over 256-row S-chunk; ksum partials ----
// 256 threads, 4x4 register tile per thread, FFMA2, 8 warps/block.
__global__ void __launch_bounds__(256) k_pass1(const float* __restrict__ K,
                                               const float* __restrict__ V,
                                               const int*   __restrict__ mask) {
    __shared__ __align__(16) float Ks[64 * 64];
    __shared__ __align__(16) float Vs[64 * 64];
    __shared__ __align__(16) float red[16 * 64];

    int tid = threadIdx.x;
    int sc = blockIdx.x, bh = blockIdx.y;
    int b = bh >> 4;
    int c4 = tid & 15, rq = tid >> 4;       // load-phase coords
    int tj = tid & 15, ti = tid >> 4;       // compute-phase coords (d=4ti.., e=4tj..)

    const float4* K4 = reinterpret_cast<const float4*>(K) + (size_t)bh * (S_ * 16);
    const float4* V4 = reinterpret_cast<const float4*>(V) + (size_t)bh * (S_ * 16);
    const int* mrow = mask + b * S_;

    float2 acc[4][2];
    #pragma unroll
    for (int d = 0; d < 4; d++) { acc[d][0] = make_float2(0.f, 0.f); acc[d][1] = make_float2(0.f, 0.f); }
    float4 ksacc = make_float4(0.f, 0.f, 0.f, 0.f);

    for (int tt = 0; tt < CH1 / 64; tt++) {
        int sbase = sc * CH1 + tt * 64;
        #pragma unroll
        for (int it = 0; it < 4; it++) {
            int rl = rq + 16 * it;
            int s = sbase + rl;
            float m = (float)mrow[s];
            float4 kv = K4[s * 16 + c4];
            float f0 = elu1(kv.x) * m;
            float f1 = elu1(kv.y) * m;
            float f2 = elu1(kv.z) * m;
            float f3 = elu1(kv.w) * m;
            ksacc.x += fabsf(f0); ksacc.y += fabsf(f1);
            ksacc.z += fabsf(f2); ksacc.w += fabsf(f3);
            if (c4 < 8) {  // rotary half (cols < 32)
                float4 t4 = g_tab4[s * 8 + c4];
                float r0 = f0 * t4.x - f1 * t4.y;
                float r1 = f1 * t4.x + f0 * t4.y;
                float r2 = f2 * t4.z - f3 * t4.w;
                float r3 = f3 * t4.z + f2 * t4.w;
                f0 = r0; f1 = r1; f2 = r2; f3 = r3;
            }
            reinterpret_cast<float4*>(Ks)[rl * 16 + c4] = make_float4(f0, f1, f2, f3);
            reinterpret_cast<float4*>(Vs)[rl * 16 + c4] = V4[s * 16 + c4];
        }
        __syncthreads();
        #pragma unroll 8
        for (int s = 0; s < 64; s++) {
            float4 kr = reinterpret_cast<const float4*>(Ks)[s * 16 + ti];
            float4 v  = reinterpret_cast<const float4*>(Vs)[s * 16 + tj];
            float2 v01 = make_float2(v.x, v.y);
            float2 v23 = make_float2(v.z, v.w);
            float2 k0 = make_float2(kr.x, kr.x);
            float2 k1 = make_float2(kr.y, kr.y);
            float2 k2 = make_float2(kr.z, kr.z);
            float2 k3 = make_float2(kr.w, kr.w);
            acc[0][0] = ffma2(k0, v01, acc[0][0]);
            acc[0][1] = ffma2(k0, v23, acc[0][1]);
            acc[1][0] = ffma2(k1, v01, acc[1][0]);
            acc[1][1] = ffma2(k1, v23, acc[1][1]);
            acc[2][0] = ffma2(k2, v01, acc[2][0]);
            acc[2][1] = ffma2(k2, v23, acc[2][1]);
            acc[3][0] = ffma2(k3, v01, acc[3][0]);
            acc[3][1] = ffma2(k3, v23, acc[3][1]);
        }
        __syncthreads();
    }

    // direct coalesced store of the 4x4 tile to split-K partials
    float4* outA4 = reinterpret_cast<float4*>(g_partA + (size_t)(bh * SC1 + sc) * 4096);
    #pragma unroll
    for (int d = 0; d < 4; d++) {
        outA4[(ti * 4 + d) * 16 + tj] =
            make_float4(acc[d][0].x, acc[d][0].y, acc[d][1].x, acc[d][1].y);
    }
    // deterministic fixed-order ksum partial reduction
    reinterpret_cast<float4*>(red)[rq * 16 + c4] = ksacc;   // red[rq][4*c4..]
    __syncthreads();
    if (tid < 64) {
        float ssum = 0.f;
        #pragma unroll
        for (int i = 0; i < 16; i++) ssum += red[i * 64 + tid];
        g_partK[(bh * SC1 + sc) * 64 + tid] = ssum;
    }
}

// ---- fixed-order split-K reduction ----
__global__ void __launch_bounds__(256) k_reduce() {
    int bh = blockIdx.x, tid = threadIdx.x;
    for (int idx = tid; idx < 4096; idx += 256) {
        float s = 0.f;
        #pragma unroll
        for (int p = 0; p < SC1; p++)
            s += g_partA[(size_t)(bh * SC1 + p) * 4096 + idx];
        g_A[bh * 4096 + idx] = s;
    }
    if (tid < 64) {
        float s = 0.f;
        #pragma unroll
        for (int p = 0; p < SC1; p++)
            s += g_partK[(bh * SC1 + p) * 64 + tid];
        g_ksum[bh * 64 + tid] = s;
    }
}

// ---- Pass 2: register-tiled GEMM. Block = 128 rows x 64 cols, thread = 8x4. ----
// dyn smem layout: As[4096] | qs[128*64] | ksm[64] | red2[256] | rinv[128]
#define P2_SMEM ((4096 + 128 * 64 + 64 + 256 + 128) * 4)
__global__ void __launch_bounds__(256, 3) k_pass2(const float* __restrict__ Q,
                                                  float* __restrict__ out) {
    extern __shared__ __align__(16) float sm[];
    float* As   = sm;                 // A[k][e], 16 KB
    float* qs   = sm + 4096;          // qs[k][row], 32 KB
    float* ksm  = qs + 128 * 64;
    float* red2 = ksm + 64;           // [2][128]
    float* rinv = red2 + 256;

    int tid = threadIdx.x;
    int st = blockIdx.x, bh = blockIdx.y;

    for (int i = tid; i < 4096; i += 256) As[i] = g_A[bh * 4096 + i];
    if (tid < 64) ksm[tid] = g_ksum[bh * 64 + tid];
    __syncthreads();

    // ---- preprocess: each thread owns half of one row (k-half) ----
    int row = tid & 127, half = tid >> 7;
    int s = st * 128 + row;
    const float4* Q4 = reinterpret_cast<const float4*>(Q)
                       + ((size_t)bh * S_ + s) * 16 + half * 8;
    float q[32];
    float nrm = 0.f;
    #pragma unroll
    for (int j = 0; j < 8; j++) {
        float4 v = Q4[j];
        float f0 = elu1(v.x * 0.125f);
        float f1 = elu1(v.y * 0.125f);
        float f2 = elu1(v.z * 0.125f);
        float f3 = elu1(v.w * 0.125f);
        int kb = half * 32 + 4 * j;
        nrm += f0 * ksm[kb] + f1 * ksm[kb + 1] + f2 * ksm[kb + 2] + f3 * ksm[kb + 3];
        q[4 * j] = f0; q[4 * j + 1] = f1; q[4 * j + 2] = f2; q[4 * j + 3] = f3;
    }
    if (half == 0) {                // rotary half: cols 0..31
        #pragma unroll
        for (int j = 0; j < 8; j++) {
            float4 t4 = g_tab4[s * 8 + j];
            float a = q[4 * j], b2 = q[4 * j + 1];
            q[4 * j]     = a * t4.x - b2 * t4.y;
            q[4 * j + 1] = b2 * t4.x + a * t4.y;
            a = q[4 * j + 2]; b2 = q[4 * j + 3];
            q[4 * j + 2] = a * t4.z - b2 * t4.w;
            q[4 * j + 3] = b2 * t4.z + a * t4.w;
        }
    }
    red2[half * 128 + row] = nrm;
    #pragma unroll
    for (int j = 0; j < 32; j++)
        qs[(half * 32 + j) * 128 + row] = q[j];
    __syncthreads();
    if (tid < 128) rinv[tid] = 1.0f / (red2[tid] + red2[128 + tid]);
    __syncthreads();

    // ---- main GEMM: thread (ty,tx) computes rows 8ty..8ty+7, cols 4tx..4tx+3 ----
    int tx = tid & 15, ty = tid >> 4;
    float2 acc[8][2];
    #pragma unroll
    for (int r = 0; r < 8; r++) { acc[r][0] = make_float2(0.f, 0.f); acc[r][1] = make_float2(0.f, 0.f); }

    #pragma unroll 8
    for (int k = 0; k < 64; k++) {
        float4 a  = reinterpret_cast<const float4*>(As)[k * 16 + tx];
        float4 r0 = reinterpret_cast<const float4*>(qs)[k * 32 + ty * 2];
        float4 r1 = reinterpret_cast<const float4*>(qs)[k * 32 + ty * 2 + 1];
        float2 a01 = make_float2(a.x, a.y);
        float2 a23 = make_float2(a.z, a.w);
        acc[0][0] = ffma2(make_float2(r0.x, r0.x), a01, acc[0][0]);
        acc[0][1] = ffma2(make_float2(r0.x, r0.x), a23, acc[0][1]);
        acc[1][0] = ffma2(make_float2(r0.y, r0.y), a01, acc[1][0]);
        acc[1][1] = ffma2(make_float2(r0.y, r0.y), a23, acc[1][1]);
        acc[2][0] = ffma2(make_float2(r0.z, r0.z), a01, acc[2][0]);
        acc[2][1] = ffma2(make_float2(r0.z, r0.z), a23, acc[2][1]);
        acc[3][0] = ffma2(make_float2(r0.w, r0.w), a01, acc[3][0]);
        acc[3][1] = ffma2(make_float2(r0.w, r0.w), a23, acc[3][1]);
        acc[4][0] = ffma2(make_float2(r1.x, r1.x), a01, acc[4][0]);
        acc[4][1] = ffma2(make_float2(r1.x, r1.x), a23, acc[4][1]);
        acc[5][0] = ffma2(make_float2(r1.y, r1.y), a01, acc[5][0]);
        acc[5][1] = ffma2(make_float2(r1.y, r1.y), a23, acc[5][1]);
        acc[6][0] = ffma2(make_float2(r1.z, r1.z), a01, acc[6][0]);
        acc[6][1] = ffma2(make_float2(r1.z, r1.z), a23, acc[6][1]);
        acc[7][0] = ffma2(make_float2(r1.w, r1.w), a01, acc[7][0]);
        acc[7][1] = ffma2(make_float2(r1.w, r1.w), a23, acc[7][1]);
    }

    float4* outp = reinterpret_cast<float4*>(out) + ((size_t)bh * S_ + st * 128) * 16;
    #pragma unroll
    for (int rr = 0; rr < 8; rr++) {
        int r = ty * 8 + rr;
        float ri = rinv[r];
        outp[r * 16 + tx] = make_float4(acc[rr][0].x * ri, acc[rr][0].y * ri,
                                        acc[rr][1].x * ri, acc[rr][1].y * ri);
    }
}

extern "C" void kernel_launch(void* const* d_in, const int* in_sizes, int n_in,
                              void* d_out, int out_size) {
    const float* Q   = (const float*)d_in[0];
    const float* K   = (const float*)d_in[1];
    const float* V   = (const float*)d_in[2];
    const int* mask  = (const int*)d_in[3];
    float* out = (float*)d_out;

    cudaFuncSetAttribute(k_pass2, cudaFuncAttributeMaxDynamicSharedMemorySize, P2_SMEM);

    k_tab<<<(S_ * 8 + 255) / 256, 256>>>();
    k_pass1<<<dim3(SC1, BH_), 256>>>(K, V, mask);
    k_reduce<<<BH_, 256>>>();
    k_pass2<<<dim3(S_ / 128, BH_), 256, P2_SMEM>>>(Q, out);
}